// round 6
// baseline (speedup 1.0000x reference)
#include <cuda_runtime.h>
#include <cstdint>

#define B_DIM 2048
#define NLEAF 1024
#define FDIM 32
#define HDIM 128
#define ODIM 32

// Ping-pong scratch for tree levels (no allocations allowed -> device globals)
__device__ __align__(256) float g_bufA[(size_t)B_DIM * NLEAF * ODIM];        // 256 MB
__device__ __align__(256) float g_bufB[(size_t)B_DIM * (NLEAF / 2) * ODIM];  // 128 MB

// ---------------- packed f32x2 helpers (sm_100+) ----------------
__device__ __forceinline__ unsigned long long pack2(float x) {
    unsigned long long r;
    asm("mov.b64 %0, {%1, %1};" : "=l"(r) : "f"(x));
    return r;
}
__device__ __forceinline__ void ffma2(unsigned long long& d, unsigned long long a,
                                      unsigned long long b) {
    asm("fma.rn.f32x2 %0, %1, %2, %3;" : "=l"(d) : "l"(a), "l"(b), "l"(d));
}

// ---------------- cooperative smem copy ----------------
__device__ __forceinline__ void copy4(float* dst, const float* __restrict__ src, int nfloats) {
    const float4* s = (const float4*)src;
    float4* d = (float4*)dst;
    int n4 = nfloats >> 2;
    for (int i = threadIdx.x; i < n4; i += blockDim.x) d[i] = s[i];
}

// ---------------- MLP layer, N=128, 64-row tile, 256 threads ----------------
// warp w (0..7) owns rows w*8..w*8+7 (TM=8). lane owns 4 contiguous cols lane*4.
// Weight load: one LDS.128/k, 32 lanes x 16B = 512B contiguous, no duplicate reads.
// Activation load: warp-uniform address LDS.128 -> broadcast (1 wavefront).
template <int K, bool RELU>
__device__ __forceinline__ void mlp_layer128(const float* __restrict__ sIn, int inLd,
                                             const float* __restrict__ sW,
                                             const float* __restrict__ sB,
                                             float* __restrict__ sOut, int outLd) {
    constexpr int TM = 8;
    constexpr int N = 128;
    const int w = threadIdx.x >> 5;
    const int lane = threadIdx.x & 31;
    const int r0 = w * TM;
    const int c0 = lane * 4;

    unsigned long long acc[TM][2];
#pragma unroll
    for (int i = 0; i < TM; i++) { acc[i][0] = 0ull; acc[i][1] = 0ull; }

    const float* wCol = sW + c0;
#pragma unroll 2
    for (int k0 = 0; k0 < K; k0 += 4) {
        float4 a[TM];
#pragma unroll
        for (int i = 0; i < TM; i++)
            a[i] = *(const float4*)(sIn + (r0 + i) * inLd + k0);
        float4 w4[4];
#pragma unroll
        for (int kk = 0; kk < 4; kk++)
            w4[kk] = *(const float4*)(wCol + (k0 + kk) * N);
#pragma unroll
        for (int kk = 0; kk < 4; kk++) {
            unsigned long long b0 = reinterpret_cast<const unsigned long long*>(&w4[kk])[0];
            unsigned long long b1 = reinterpret_cast<const unsigned long long*>(&w4[kk])[1];
#pragma unroll
            for (int i = 0; i < TM; i++) {
                float av = (kk == 0) ? a[i].x : (kk == 1) ? a[i].y : (kk == 2) ? a[i].z : a[i].w;
                unsigned long long ap = pack2(av);
                ffma2(acc[i][0], ap, b0);
                ffma2(acc[i][1], ap, b1);
            }
        }
    }

    float4 bb = *(const float4*)(sB + c0);
#pragma unroll
    for (int i = 0; i < TM; i++) {
        float2 v0 = *reinterpret_cast<float2*>(&acc[i][0]);
        float2 v1 = *reinterpret_cast<float2*>(&acc[i][1]);
        float4 o;
        o.x = v0.x + bb.x; o.y = v0.y + bb.y; o.z = v1.x + bb.z; o.w = v1.y + bb.w;
        if (RELU) {
            o.x = fmaxf(o.x, 0.f); o.y = fmaxf(o.y, 0.f);
            o.z = fmaxf(o.z, 0.f); o.w = fmaxf(o.w, 0.f);
        }
        *(float4*)(sOut + (r0 + i) * outLd + c0) = o;
    }
}

// ---------------- MLP layer, N=32 (final), scalar col per lane ----------------
template <int K, bool RELU>
__device__ __forceinline__ void mlp_layer32(const float* __restrict__ sIn, int inLd,
                                            const float* __restrict__ sW,
                                            const float* __restrict__ sB,
                                            float* __restrict__ sOut, int outLd) {
    constexpr int TM = 8;
    constexpr int N = 32;
    const int w = threadIdx.x >> 5;
    const int lane = threadIdx.x & 31;
    const int r0 = w * TM;

    float acc[TM];
#pragma unroll
    for (int i = 0; i < TM; i++) acc[i] = 0.f;

    const float* wCol = sW + lane;
#pragma unroll 2
    for (int k0 = 0; k0 < K; k0 += 4) {
        float4 a[TM];
#pragma unroll
        for (int i = 0; i < TM; i++)
            a[i] = *(const float4*)(sIn + (r0 + i) * inLd + k0);
        float wv[4];
#pragma unroll
        for (int kk = 0; kk < 4; kk++) wv[kk] = wCol[(k0 + kk) * N];
#pragma unroll
        for (int kk = 0; kk < 4; kk++) {
#pragma unroll
            for (int i = 0; i < TM; i++) {
                float av = (kk == 0) ? a[i].x : (kk == 1) ? a[i].y : (kk == 2) ? a[i].z : a[i].w;
                acc[i] = fmaf(av, wv[kk], acc[i]);
            }
        }
    }

    float bb = sB[lane];
#pragma unroll
    for (int i = 0; i < TM; i++) {
        float o = acc[i] + bb;
        if (RELU) o = fmaxf(o, 0.f);
        sOut[(r0 + i) * outLd + lane] = o;
    }
}

// ---------------- leaf stage: (M,32) -> 32->128->128->32 ----------------
__global__ void __launch_bounds__(256, 1)
    leaf_kernel(const float* __restrict__ X, const float* __restrict__ W1,
                const float* __restrict__ B1, const float* __restrict__ W2,
                const float* __restrict__ B2, const float* __restrict__ W3,
                const float* __restrict__ B3, float* __restrict__ Y, int numTiles) {
    extern __shared__ float sm[];
    float* sW1 = sm;                 // 32*128
    float* sW2 = sW1 + 32 * 128;     // 128*128
    float* sW3 = sW2 + 128 * 128;    // 128*32
    float* sB1 = sW3 + 128 * 32;     // 128
    float* sB2 = sB1 + 128;          // 128
    float* sB3 = sB2 + 128;          // 32
    float* sX = sB3 + 32;            // 64*36 (padded)
    float* sH1 = sX + 64 * 36;       // 64*132 (padded)
    float* sH2 = sH1 + 64 * 132;     // 64*132

    copy4(sW1, W1, 32 * 128);
    copy4(sW2, W2, 128 * 128);
    copy4(sW3, W3, 128 * 32);
    copy4(sB1, B1, 128);
    copy4(sB2, B2, 128);
    copy4(sB3, B3, 32);
    __syncthreads();

    const int t = threadIdx.x;
    for (int tile = blockIdx.x; tile < numTiles; tile += gridDim.x) {
        const float4* src = (const float4*)(X + (size_t)tile * 64 * 32);
#pragma unroll
        for (int i = 0; i < 2; i++) {
            int idx = t + i * 256;  // 512 float4 = 64 rows x 8
            int row = idx >> 3, q = idx & 7;
            *(float4*)(sX + row * 36 + q * 4) = src[idx];
        }
        __syncthreads();
        mlp_layer128<32, true>(sX, 36, sW1, sB1, sH1, 132);
        __syncthreads();
        mlp_layer128<128, true>(sH1, 132, sW2, sB2, sH2, 132);
        __syncthreads();
        mlp_layer32<128, false>(sH2, 132, sW3, sB3, sH1, 36);
        __syncthreads();
        float4* dstv = (float4*)(Y + (size_t)tile * 64 * 32);
#pragma unroll
        for (int i = 0; i < 2; i++) {
            int idx = t + i * 256;
            int row = idx >> 3, q = idx & 7;
            dstv[idx] = *(float4*)(sH1 + row * 36 + q * 4);
        }
        __syncthreads();
    }
}

// ---------------- join stage: concat(feats32, children64) -> 96->128->128->32 ----
__global__ void __launch_bounds__(256, 1)
    join_kernel(const float* __restrict__ internal, int off, int nShift,
                const float* __restrict__ prev, const float* __restrict__ W1,
                const float* __restrict__ B1, const float* __restrict__ W2,
                const float* __restrict__ B2, const float* __restrict__ W3,
                const float* __restrict__ B3, float* __restrict__ Y, int numTiles) {
    extern __shared__ float sm[];
    float* sW1 = sm;                 // 96*128
    float* sW2 = sW1 + 96 * 128;     // 128*128
    float* sW3 = sW2 + 128 * 128;    // 128*32
    float* sB1 = sW3 + 128 * 32;
    float* sB2 = sB1 + 128;
    float* sB3 = sB2 + 128;
    float* sX = sB3 + 32;            // 64*100 (padded 96->100)
    float* sH1 = sX + 64 * 100;      // 64*132
    float* sH2 = sH1 + 64 * 132;     // 64*132

    copy4(sW1, W1, 96 * 128);
    copy4(sW2, W2, 128 * 128);
    copy4(sW3, W3, 128 * 32);
    copy4(sB1, B1, 128);
    copy4(sB2, B2, 128);
    copy4(sB3, B3, 32);
    __syncthreads();

    const int t = threadIdx.x;
    const int nMask = (1 << nShift) - 1;
    const int row = t >> 2;        // 4 threads per row
    const int sub = t & 3;         // each does 6 float4 of the 24/row

    for (int tile = blockIdx.x; tile < numTiles; tile += gridDim.x) {
        // assemble xin row = [feats(32) | child0(32) | child1(32)]
        {
            int m = tile * 64 + row;
            int bidx = m >> nShift;
            int i = m & nMask;
            const float4* frow =
                (const float4*)(internal + ((size_t)bidx * (NLEAF - 1) + off + i) * FDIM);
            const float4* crow =
                (const float4*)(prev + ((size_t)(bidx << (nShift + 1)) + 2 * (size_t)i) * ODIM);
#pragma unroll
            for (int jj = 0; jj < 6; jj++) {
                int q = sub * 6 + jj;  // 0..23
                float4 v = (q < 8) ? frow[q] : crow[q - 8];
                *(float4*)(sX + row * 100 + q * 4) = v;
            }
        }
        __syncthreads();
        mlp_layer128<96, true>(sX, 100, sW1, sB1, sH1, 132);
        __syncthreads();
        mlp_layer128<128, true>(sH1, 132, sW2, sB2, sH2, 132);
        __syncthreads();
        mlp_layer32<128, false>(sH2, 132, sW3, sB3, sX, 36);
        __syncthreads();
        float4* dstv = (float4*)(Y + (size_t)tile * 64 * 32);
#pragma unroll
        for (int i = 0; i < 2; i++) {
            int idx = t + i * 256;
            int r2 = idx >> 3, q = idx & 7;
            dstv[idx] = *(float4*)(sX + r2 * 36 + q * 4);
        }
        __syncthreads();
    }
}

__global__ void gather_kernel(const float* __restrict__ src, float* __restrict__ out) {
    int b = blockIdx.x * blockDim.x + threadIdx.x;
    if (b < B_DIM) out[b] = src[(size_t)b * ODIM];
}

extern "C" void kernel_launch(void* const* d_in, const int* in_sizes, int n_in, void* d_out,
                              int out_size) {
    const float* leaf = (const float*)d_in[0];
    const float* internal = (const float*)d_in[1];
    const float* sW1 = (const float*)d_in[2];
    const float* sb1 = (const float*)d_in[3];
    const float* sW2 = (const float*)d_in[4];
    const float* sb2 = (const float*)d_in[5];
    const float* sW3 = (const float*)d_in[6];
    const float* sb3 = (const float*)d_in[7];
    const float* jW1 = (const float*)d_in[8];
    const float* jb1 = (const float*)d_in[9];
    const float* jW2 = (const float*)d_in[10];
    const float* jb2 = (const float*)d_in[11];
    const float* jW3 = (const float*)d_in[12];
    const float* jb3 = (const float*)d_in[13];
    float* out = (float*)d_out;

    float *bufA, *bufB;
    cudaGetSymbolAddress((void**)&bufA, g_bufA);
    cudaGetSymbolAddress((void**)&bufB, g_bufB);

    const int leafSm =
        (32 * 128 + 128 * 128 + 128 * 32 + 128 + 128 + 32 + 64 * 36 + 2 * 64 * 132) * 4;
    const int joinSm =
        (96 * 128 + 128 * 128 + 128 * 32 + 128 + 128 + 32 + 64 * 100 + 2 * 64 * 132) * 4;
    cudaFuncSetAttribute(leaf_kernel, cudaFuncAttributeMaxDynamicSharedMemorySize, leafSm);
    cudaFuncSetAttribute(join_kernel, cudaFuncAttributeMaxDynamicSharedMemorySize, joinSm);

    int sms = 148;
    cudaDeviceGetAttribute(&sms, cudaDevAttrMultiProcessorCount, 0);

    const int leafTiles = (B_DIM * NLEAF) / 64;  // 32768
    leaf_kernel<<<sms, 256, leafSm>>>(leaf, sW1, sb1, sW2, sb2, sW3, sb3, bufA, leafTiles);

    float* src = bufA;
    float* dst = bufB;
    int off = 0;
    for (int sh = 9; sh >= 0; sh--) {
        int n = 1 << sh;
        int tiles = (B_DIM * n) / 64;
        join_kernel<<<sms, 256, joinSm>>>(internal, off, sh, src, jW1, jb1, jW2, jb2, jW3, jb3,
                                          dst, tiles);
        off += n;
        float* tmp = src;
        src = dst;
        dst = tmp;
    }
    gather_kernel<<<(B_DIM + 255) / 256, 256>>>(src, out);
}

// round 10
// speedup vs baseline: 2.2904x; 2.2904x over previous
#include <cuda_runtime.h>
#include <cuda_bf16.h>
#include <cstdint>

#define B_DIM 2048
#define NLEAF 1024

// ---------------- device scratch (no allocations allowed) ----------------
__device__ __align__(256) float g_bufA[(size_t)B_DIM * NLEAF * 32];        // 256 MB
__device__ __align__(256) float g_bufB[(size_t)B_DIM * (NLEAF / 2) * 32];  // 128 MB
// per-MLP weight stage: W1t hi/lo [128][104], W2t hi/lo [128][136], W3t hi/lo [32][136]
#define W1_ELEMS 13312  // 128*104
#define W2_ELEMS 17408  // 128*136
#define W3_ELEMS 4352   // 32*136
#define STAGE_BYTES 140288
__device__ __align__(256) unsigned char g_wstage[2 * STAGE_BYTES];

// ---------------- smem layout (bytes) ----------------
#define OFF_W1H 0
#define OFF_W1L 26624
#define OFF_W2H 53248
#define OFF_W2L 88064
#define OFF_W3H 122880
#define OFF_W3L 131584
#define OFF_BIAS 140288  // b1(128f) b2(128f) b3(32f) = 1152B
#define OFF_AHI 141440   // 128 rows x 136 bf16 = 34816B
#define OFF_ALO 176256
#define SM_BYTES 211072

#define A_STRIDE 272  // bytes per A row (136 bf16); 272 % 128 = 16 -> conflict-free LDSM
#define W1_KP 104     // 208B stride; 208 % 128 = 80 -> conflict-free
#define W23_KP 136

// ---------------- PTX helpers (base-arch only: ldmatrix + mma.sync) ----------------
__device__ __forceinline__ uint32_t smem_u32(const void* p) {
    uint32_t a;
    asm("{ .reg .u64 t; cvta.to.shared.u64 t, %1; cvt.u32.u64 %0, t; }" : "=r"(a) : "l"(p));
    return a;
}
__device__ __forceinline__ uint4 ldsm4(uint32_t a) {
    uint4 r;
    asm volatile("ldmatrix.sync.aligned.m8n8.x4.shared.b16 {%0,%1,%2,%3}, [%4];"
                 : "=r"(r.x), "=r"(r.y), "=r"(r.z), "=r"(r.w)
                 : "r"(a));
    return r;
}
__device__ __forceinline__ uint2 ldsm2(uint32_t a) {
    uint2 r;
    asm volatile("ldmatrix.sync.aligned.m8n8.x2.shared.b16 {%0,%1}, [%2];"
                 : "=r"(r.x), "=r"(r.y)
                 : "r"(a));
    return r;
}
__device__ __forceinline__ void mma_bf16(float* c, const uint4& a, const uint2& b) {
    asm volatile(
        "mma.sync.aligned.m16n8k16.row.col.f32.bf16.bf16.f32 "
        "{%0,%1,%2,%3}, {%4,%5,%6,%7}, {%8,%9}, {%0,%1,%2,%3};"
        : "+f"(c[0]), "+f"(c[1]), "+f"(c[2]), "+f"(c[3])
        : "r"(a.x), "r"(a.y), "r"(a.z), "r"(a.w), "r"(b.x), "r"(b.y));
}

// ---------------- bf16 hi/lo split ----------------
__device__ __forceinline__ void split2(float x, float y, uint32_t& h, uint32_t& l) {
    __nv_bfloat16 hx = __float2bfloat16(x), hy = __float2bfloat16(y);
    float rx = x - __bfloat162float(hx), ry = y - __bfloat162float(hy);
    __nv_bfloat16 lx = __float2bfloat16(rx), ly = __float2bfloat16(ry);
    h = (uint32_t)__bfloat16_as_ushort(hx) | ((uint32_t)__bfloat16_as_ushort(hy) << 16);
    l = (uint32_t)__bfloat16_as_ushort(lx) | ((uint32_t)__bfloat16_as_ushort(ly) << 16);
}
// store 4 consecutive k of row into A_hi/A_lo (row-major, stride 136 bf16)
__device__ __forceinline__ void store4A(char* aHi, char* aLo, int row, int k, float4 v) {
    uint32_t h0, l0, h1, l1;
    split2(v.x, v.y, h0, l0);
    split2(v.z, v.w, h1, l1);
    uint32_t off = (uint32_t)row * A_STRIDE + (uint32_t)k * 2;
    *(uint2*)(aHi + off) = make_uint2(h0, h1);
    *(uint2*)(aLo + off) = make_uint2(l0, l1);
}

__device__ __forceinline__ void copy4(float* dst, const float* __restrict__ src, int nfloats) {
    const float4* s = (const float4*)src;
    float4* d = (float4*)dst;
    int n4 = nfloats >> 2;
    for (int i = threadIdx.x; i < n4; i += blockDim.x) d[i] = s[i];
}

// ---------------- one layer: C[32 x (NTILES*8)] per warp, 3-term split ----------------
template <int NK, int NTILES, int WKP>
__device__ __forceinline__ void layer_mma(uint32_t aHiB, uint32_t aLoB, uint32_t wHiB,
                                          uint32_t wLoB, float c[2][NTILES][4], int m0, int n0) {
    const int lane = threadIdx.x & 31;
#pragma unroll
    for (int mt = 0; mt < 2; mt++)
#pragma unroll
        for (int nt = 0; nt < NTILES; nt++)
#pragma unroll
            for (int j = 0; j < 4; j++) c[mt][nt][j] = 0.f;

    uint32_t aOff = (uint32_t)(m0 + (lane & 15)) * A_STRIDE + (uint32_t)((lane >> 4) << 4);
    uint32_t aH = aHiB + aOff, aL = aLoB + aOff;
    uint32_t wOff = (uint32_t)(n0 + (lane & 7)) * (WKP * 2) + (uint32_t)(((lane >> 3) & 1) << 4);
    uint32_t wH = wHiB + wOff, wL = wLoB + wOff;

#pragma unroll 1
    for (int ks = 0; ks < NK; ks++) {
        uint32_t ka = (uint32_t)ks * 32;
        uint4 ah0 = ldsm4(aH + ka);
        uint4 ah1 = ldsm4(aH + 16 * A_STRIDE + ka);
        uint4 al0 = ldsm4(aL + ka);
        uint4 al1 = ldsm4(aL + 16 * A_STRIDE + ka);
#pragma unroll
        for (int nt = 0; nt < NTILES; nt++) {
            uint2 bh = ldsm2(wH + (uint32_t)nt * 8 * (WKP * 2) + ka);
            uint2 bl = ldsm2(wL + (uint32_t)nt * 8 * (WKP * 2) + ka);
            mma_bf16(c[0][nt], ah0, bh);
            mma_bf16(c[0][nt], ah0, bl);
            mma_bf16(c[0][nt], al0, bh);
            mma_bf16(c[1][nt], ah1, bh);
            mma_bf16(c[1][nt], ah1, bl);
            mma_bf16(c[1][nt], al1, bh);
        }
    }
}

// epilogue: bias (+relu), split to bf16 hi/lo, store back into A buffers
template <int NTILES, bool RELU>
__device__ __forceinline__ void epi_to_A(float c[2][NTILES][4], const float* sBias, char* aHi,
                                         char* aLo, int m0, int n0) {
    const int lane = threadIdx.x & 31;
    const int cb = n0 + (lane & 3) * 2;
    const int r0 = m0 + (lane >> 2);
#pragma unroll
    for (int mt = 0; mt < 2; mt++) {
#pragma unroll
        for (int nt = 0; nt < NTILES; nt++) {
            int col = cb + nt * 8;
            float2 bb = *(const float2*)(sBias + col);
            float v0 = c[mt][nt][0] + bb.x, v1 = c[mt][nt][1] + bb.y;
            float v2 = c[mt][nt][2] + bb.x, v3 = c[mt][nt][3] + bb.y;
            if (RELU) {
                v0 = fmaxf(v0, 0.f); v1 = fmaxf(v1, 0.f);
                v2 = fmaxf(v2, 0.f); v3 = fmaxf(v3, 0.f);
            }
            int r = r0 + mt * 16;
            uint32_t h, l;
            split2(v0, v1, h, l);
            *(uint32_t*)(aHi + (uint32_t)r * A_STRIDE + col * 2) = h;
            *(uint32_t*)(aLo + (uint32_t)r * A_STRIDE + col * 2) = l;
            split2(v2, v3, h, l);
            *(uint32_t*)(aHi + (uint32_t)(r + 8) * A_STRIDE + col * 2) = h;
            *(uint32_t*)(aLo + (uint32_t)(r + 8) * A_STRIDE + col * 2) = l;
        }
    }
}

// ---------------- weight prep: transpose [k][n]->[n][k], split hi/lo, pad ----------------
__global__ void prep_weights(const float* __restrict__ sW1, const float* __restrict__ sW2,
                             const float* __restrict__ sW3, const float* __restrict__ jW1,
                             const float* __restrict__ jW2, const float* __restrict__ jW3) {
    int idx = blockIdx.x * blockDim.x + threadIdx.x;
    if (idx >= W1_ELEMS + W2_ELEMS + W3_ELEMS) return;
    int mlp = blockIdx.y;
    const float* W;
    int n, k, Kp, Kreal, N, hiE, loE;
    if (idx < W1_ELEMS) {
        Kp = W1_KP; n = idx / Kp; k = idx % Kp; N = 128;
        Kreal = mlp ? 96 : 32;
        W = mlp ? jW1 : sW1;
        hiE = 0; loE = W1_ELEMS;
    } else if (idx < W1_ELEMS + W2_ELEMS) {
        int li = idx - W1_ELEMS;
        Kp = W23_KP; n = li / Kp; k = li % Kp; N = 128;
        Kreal = 128;
        W = mlp ? jW2 : sW2;
        hiE = 2 * W1_ELEMS; loE = 2 * W1_ELEMS + W2_ELEMS;
    } else {
        int li = idx - W1_ELEMS - W2_ELEMS;
        Kp = W23_KP; n = li / Kp; k = li % Kp; N = 32;
        Kreal = 128;
        W = mlp ? jW3 : sW3;
        hiE = 2 * W1_ELEMS + 2 * W2_ELEMS; loE = hiE + W3_ELEMS;
    }
    float w = (k < Kreal) ? W[k * N + n] : 0.f;
    __nv_bfloat16 bh = __float2bfloat16(w);
    float r = w - __bfloat162float(bh);
    __nv_bfloat16 bl = __float2bfloat16(r);
    __nv_bfloat16* base = (__nv_bfloat16*)(g_wstage + (size_t)mlp * STAGE_BYTES);
    base[hiE + n * Kp + k] = bh;
    base[loE + n * Kp + k] = bl;
}

// ---------------- main tile kernel: 128-row tiles through the 3-layer MLP ----------------
template <bool JOIN, int NK1>
__global__ void __launch_bounds__(256, 1)
    mlp3_kernel(const float* __restrict__ feats, int off, int nShift, const float* __restrict__ prev,
                const float* __restrict__ b1, const float* __restrict__ b2,
                const float* __restrict__ b3, float* __restrict__ Y, int numTiles, int mlpIdx) {
    extern __shared__ char sm[];
    float* smF = (float*)sm;

    copy4(smF, (const float*)(g_wstage + (size_t)mlpIdx * STAGE_BYTES), STAGE_BYTES / 4);
    copy4(smF + OFF_BIAS / 4, b1, 128);
    copy4(smF + OFF_BIAS / 4 + 128, b2, 128);
    copy4(smF + OFF_BIAS / 4 + 256, b3, 32);
    __syncthreads();

    const uint32_t su = smem_u32(sm);
    char* aHi = sm + OFF_AHI;
    char* aLo = sm + OFF_ALO;
    const float* sB1 = smF + OFF_BIAS / 4;
    const float* sB2 = sB1 + 128;
    const float* sB3 = sB2 + 128;

    const int t = threadIdx.x;
    const int wid = t >> 5;
    const int lane = t & 31;
    const int m0 = (wid >> 1) * 32;
    const int n064 = (wid & 1) * 64;
    const int n016 = (wid & 1) * 16;
    const int arow = t >> 1;   // assembly: 2 threads per row
    const int ahalf = t & 1;

    float c[2][8][4];
    float c3[2][2][4];

    for (int tile = blockIdx.x; tile < numTiles; tile += gridDim.x) {
        // ---- assemble layer-1 input (bf16 hi/lo) ----
        if (JOIN) {
            int g = tile * 128 + arow;
            int bidx = g >> nShift, i = g & ((1 << nShift) - 1);
            const float4* frow =
                (const float4*)(feats + ((size_t)bidx * (NLEAF - 1) + off + i) * 32);
            const float4* crow =
                (const float4*)(prev + (((size_t)bidx << (nShift + 1)) + 2 * (size_t)i) * 32);
            int q0 = ahalf * 12;
#pragma unroll
            for (int jj = 0; jj < 12; jj++) {
                int q = q0 + jj;
                float4 v = (q < 8) ? frow[q] : crow[q - 8];
                store4A(aHi, aLo, arow, q * 4, v);
            }
        } else {
            const float4* xr = (const float4*)(feats + ((size_t)tile * 128 + arow) * 32);
            int q0 = ahalf * 4;
#pragma unroll
            for (int jj = 0; jj < 4; jj++) {
                int q = q0 + jj;
                store4A(aHi, aLo, arow, q * 4, xr[q]);
            }
        }
        __syncthreads();

        // ---- layer 1 ----
        layer_mma<NK1, 8, W1_KP>(su + OFF_AHI, su + OFF_ALO, su + OFF_W1H, su + OFF_W1L, c, m0,
                                 n064);
        __syncthreads();
        epi_to_A<8, true>(c, sB1, aHi, aLo, m0, n064);
        __syncthreads();

        // ---- layer 2 ----
        layer_mma<8, 8, W23_KP>(su + OFF_AHI, su + OFF_ALO, su + OFF_W2H, su + OFF_W2L, c, m0,
                                n064);
        __syncthreads();
        epi_to_A<8, true>(c, sB2, aHi, aLo, m0, n064);
        __syncthreads();

        // ---- layer 3 (N=32, no relu) -> gmem ----
        layer_mma<8, 2, W23_KP>(su + OFF_AHI, su + OFF_ALO, su + OFF_W3H, su + OFF_W3L, c3, m0,
                                n016);
        __syncthreads();  // A reads done before next tile's assembly overwrites
        {
            const int cb = n016 + (lane & 3) * 2;
            const int r0 = m0 + (lane >> 2);
#pragma unroll
            for (int mt = 0; mt < 2; mt++) {
#pragma unroll
                for (int nt = 0; nt < 2; nt++) {
                    int col = cb + nt * 8;
                    float2 bb = *(const float2*)(sB3 + col);
                    int r = r0 + mt * 16;
                    float2 o0 = make_float2(c3[mt][nt][0] + bb.x, c3[mt][nt][1] + bb.y);
                    float2 o1 = make_float2(c3[mt][nt][2] + bb.x, c3[mt][nt][3] + bb.y);
                    *(float2*)(Y + ((size_t)tile * 128 + r) * 32 + col) = o0;
                    *(float2*)(Y + ((size_t)tile * 128 + r + 8) * 32 + col) = o1;
                }
            }
        }
    }
}

__global__ void gather_kernel(const float* __restrict__ src, float* __restrict__ out) {
    int b = blockIdx.x * blockDim.x + threadIdx.x;
    if (b < B_DIM) out[b] = src[(size_t)b * 32];
}

extern "C" void kernel_launch(void* const* d_in, const int* in_sizes, int n_in, void* d_out,
                              int out_size) {
    const float* leaf = (const float*)d_in[0];
    const float* internal = (const float*)d_in[1];
    const float* sW1 = (const float*)d_in[2];
    const float* sb1 = (const float*)d_in[3];
    const float* sW2 = (const float*)d_in[4];
    const float* sb2 = (const float*)d_in[5];
    const float* sW3 = (const float*)d_in[6];
    const float* sb3 = (const float*)d_in[7];
    const float* jW1 = (const float*)d_in[8];
    const float* jb1 = (const float*)d_in[9];
    const float* jW2 = (const float*)d_in[10];
    const float* jb2 = (const float*)d_in[11];
    const float* jW3 = (const float*)d_in[12];
    const float* jb3 = (const float*)d_in[13];
    float* out = (float*)d_out;

    float *bufA, *bufB;
    cudaGetSymbolAddress((void**)&bufA, g_bufA);
    cudaGetSymbolAddress((void**)&bufB, g_bufB);

    cudaFuncSetAttribute(mlp3_kernel<false, 2>, cudaFuncAttributeMaxDynamicSharedMemorySize,
                         SM_BYTES);
    cudaFuncSetAttribute(mlp3_kernel<true, 6>, cudaFuncAttributeMaxDynamicSharedMemorySize,
                         SM_BYTES);

    int sms = 148;
    cudaDeviceGetAttribute(&sms, cudaDevAttrMultiProcessorCount, 0);

    const int totalW = W1_ELEMS + W2_ELEMS + W3_ELEMS;
    prep_weights<<<dim3((totalW + 255) / 256, 2), 256>>>(sW1, sW2, sW3, jW1, jW2, jW3);

    // leaf: 2048*1024 rows / 128 = 16384 tiles
    mlp3_kernel<false, 2><<<sms, 256, SM_BYTES>>>(leaf, 0, 0, nullptr, sb1, sb2, sb3, bufA, 16384,
                                                  0);

    float* src = bufA;
    float* dst = bufB;
    int off = 0;
    for (int sh = 9; sh >= 0; sh--) {
        int n = 1 << sh;
        int tiles = 16 * n;  // 2048*n/128
        mlp3_kernel<true, 6><<<sms, 256, SM_BYTES>>>(internal, off, sh, src, jb1, jb2, jb3, dst,
                                                     tiles, 1);
        off += n;
        float* tmp = src;
        src = dst;
        dst = tmp;
    }
    gather_kernel<<<(B_DIM + 255) / 256, 256>>>(src, out);
}

// round 12
// speedup vs baseline: 2.6026x; 1.1363x over previous
#include <cuda_runtime.h>
#include <cuda_bf16.h>
#include <cstdint>

#define B_DIM 2048
#define NLEAF 1024

// ---------------- device scratch (no allocations allowed) ----------------
__device__ __align__(256) float g_bufA[(size_t)B_DIM * NLEAF * 32];        // 256 MB
__device__ __align__(256) float g_bufB[(size_t)B_DIM * (NLEAF / 2) * 32];  // 128 MB
// per-MLP weight stage: W1t hi/lo [128][104], W2t hi/lo [128][136], W3t hi/lo [32][136]
#define W1_ELEMS 13312  // 128*104
#define W2_ELEMS 17408  // 128*136
#define W3_ELEMS 4352   // 32*136
#define STAGE_BYTES 140288
__device__ __align__(256) unsigned char g_wstage[2 * STAGE_BYTES];

// ---------------- smem layout (bytes) ----------------
#define OFF_W1H 0
#define OFF_W1L 26624
#define OFF_W2H 53248
#define OFF_W2L 88064
#define OFF_W3H 122880
#define OFF_W3L 131584
#define OFF_BIAS 140288  // b1(128f) b2(128f) b3(32f) = 1152B
#define OFF_A 141440     // 2 groups x (64x136 bf16 hi + lo) = 2 x 34816
#define GRP_A_BYTES 34816
#define GRP_A_LO 17408
#define SM_BYTES 211072

#define A_STRIDE 272  // bytes per A row (136 bf16); 272 % 128 = 16 -> conflict-free LDSM
#define W1_KP 104     // 208B stride; 208 % 128 = 80 -> conflict-free
#define W23_KP 136

// ---------------- PTX helpers (base-arch only: ldmatrix + mma.sync) ----------------
__device__ __forceinline__ uint32_t smem_u32(const void* p) {
    uint32_t a;
    asm("{ .reg .u64 t; cvta.to.shared.u64 t, %1; cvt.u32.u64 %0, t; }" : "=r"(a) : "l"(p));
    return a;
}
__device__ __forceinline__ void bar_grp(int g) {
    asm volatile("bar.sync %0, 128;" ::"r"(g + 1) : "memory");
}
__device__ __forceinline__ uint4 ldsm4(uint32_t a) {
    uint4 r;
    asm volatile("ldmatrix.sync.aligned.m8n8.x4.shared.b16 {%0,%1,%2,%3}, [%4];"
                 : "=r"(r.x), "=r"(r.y), "=r"(r.z), "=r"(r.w)
                 : "r"(a));
    return r;
}
__device__ __forceinline__ uint2 ldsm2(uint32_t a) {
    uint2 r;
    asm volatile("ldmatrix.sync.aligned.m8n8.x2.shared.b16 {%0,%1}, [%2];"
                 : "=r"(r.x), "=r"(r.y)
                 : "r"(a));
    return r;
}
__device__ __forceinline__ void mma_bf16(float* c, const uint4& a, const uint2& b) {
    asm volatile(
        "mma.sync.aligned.m16n8k16.row.col.f32.bf16.bf16.f32 "
        "{%0,%1,%2,%3}, {%4,%5,%6,%7}, {%8,%9}, {%0,%1,%2,%3};"
        : "+f"(c[0]), "+f"(c[1]), "+f"(c[2]), "+f"(c[3])
        : "r"(a.x), "r"(a.y), "r"(a.z), "r"(a.w), "r"(b.x), "r"(b.y));
}

// ---------------- bf16 hi/lo split ----------------
__device__ __forceinline__ void split2(float x, float y, uint32_t& h, uint32_t& l) {
    __nv_bfloat16 hx = __float2bfloat16(x), hy = __float2bfloat16(y);
    float rx = x - __bfloat162float(hx), ry = y - __bfloat162float(hy);
    __nv_bfloat16 lx = __float2bfloat16(rx), ly = __float2bfloat16(ry);
    h = (uint32_t)__bfloat16_as_ushort(hx) | ((uint32_t)__bfloat16_as_ushort(hy) << 16);
    l = (uint32_t)__bfloat16_as_ushort(lx) | ((uint32_t)__bfloat16_as_ushort(ly) << 16);
}
// store 4 consecutive k of row into A_hi/A_lo (row-major, stride 136 bf16)
__device__ __forceinline__ void store4A(char* aHi, char* aLo, int row, int k, float4 v) {
    uint32_t h0, l0, h1, l1;
    split2(v.x, v.y, h0, l0);
    split2(v.z, v.w, h1, l1);
    uint32_t off = (uint32_t)row * A_STRIDE + (uint32_t)k * 2;
    *(uint2*)(aHi + off) = make_uint2(h0, h1);
    *(uint2*)(aLo + off) = make_uint2(l0, l1);
}

__device__ __forceinline__ void copy4(float* dst, const float* __restrict__ src, int nfloats) {
    const float4* s = (const float4*)src;
    float4* d = (float4*)dst;
    int n4 = nfloats >> 2;
    for (int i = threadIdx.x; i < n4; i += blockDim.x) d[i] = s[i];
}

// ---------------- one layer: per-warp C[32 x (NTILES*8)], 3-term split ----------------
// group-local: 2 warps per group dimension m (m0 in {0,32} covers 64 rows),
// n split across wg>>1.
template <int NK, int NTILES, int WKP>
__device__ __forceinline__ void layer_mma(uint32_t aHiB, uint32_t aLoB, uint32_t wHiB,
                                          uint32_t wLoB, float c[2][NTILES][4], int m0, int n0) {
    const int lane = threadIdx.x & 31;
#pragma unroll
    for (int mt = 0; mt < 2; mt++)
#pragma unroll
        for (int nt = 0; nt < NTILES; nt++)
#pragma unroll
            for (int j = 0; j < 4; j++) c[mt][nt][j] = 0.f;

    uint32_t aOff = (uint32_t)(m0 + (lane & 15)) * A_STRIDE + (uint32_t)((lane >> 4) << 4);
    uint32_t aH = aHiB + aOff, aL = aLoB + aOff;
    uint32_t wOff = (uint32_t)(n0 + (lane & 7)) * (WKP * 2) + (uint32_t)(((lane >> 3) & 1) << 4);
    uint32_t wH = wHiB + wOff, wL = wLoB + wOff;

#pragma unroll 1
    for (int ks = 0; ks < NK; ks++) {
        uint32_t ka = (uint32_t)ks * 32;
        uint4 ah0 = ldsm4(aH + ka);
        uint4 ah1 = ldsm4(aH + 16 * A_STRIDE + ka);
        uint4 al0 = ldsm4(aL + ka);
        uint4 al1 = ldsm4(aL + 16 * A_STRIDE + ka);
#pragma unroll
        for (int nt = 0; nt < NTILES; nt++) {
            uint2 bh = ldsm2(wH + (uint32_t)nt * 8 * (WKP * 2) + ka);
            uint2 bl = ldsm2(wL + (uint32_t)nt * 8 * (WKP * 2) + ka);
            mma_bf16(c[0][nt], ah0, bh);
            mma_bf16(c[0][nt], ah0, bl);
            mma_bf16(c[0][nt], al0, bh);
            mma_bf16(c[1][nt], ah1, bh);
            mma_bf16(c[1][nt], ah1, bl);
            mma_bf16(c[1][nt], al1, bh);
        }
    }
}

// epilogue: bias (+relu), split to bf16 hi/lo, store back into A buffers
template <int NTILES, bool RELU>
__device__ __forceinline__ void epi_to_A(float c[2][NTILES][4], const float* sBias, char* aHi,
                                         char* aLo, int m0, int n0) {
    const int lane = threadIdx.x & 31;
    const int cb = n0 + (lane & 3) * 2;
    const int r0 = m0 + (lane >> 2);
#pragma unroll
    for (int mt = 0; mt < 2; mt++) {
#pragma unroll
        for (int nt = 0; nt < NTILES; nt++) {
            int col = cb + nt * 8;
            float2 bb = *(const float2*)(sBias + col);
            float v0 = c[mt][nt][0] + bb.x, v1 = c[mt][nt][1] + bb.y;
            float v2 = c[mt][nt][2] + bb.x, v3 = c[mt][nt][3] + bb.y;
            if (RELU) {
                v0 = fmaxf(v0, 0.f); v1 = fmaxf(v1, 0.f);
                v2 = fmaxf(v2, 0.f); v3 = fmaxf(v3, 0.f);
            }
            int r = r0 + mt * 16;
            uint32_t h, l;
            split2(v0, v1, h, l);
            *(uint32_t*)(aHi + (uint32_t)r * A_STRIDE + col * 2) = h;
            *(uint32_t*)(aLo + (uint32_t)r * A_STRIDE + col * 2) = l;
            split2(v2, v3, h, l);
            *(uint32_t*)(aHi + (uint32_t)(r + 8) * A_STRIDE + col * 2) = h;
            *(uint32_t*)(aLo + (uint32_t)(r + 8) * A_STRIDE + col * 2) = l;
        }
    }
}

// ---------------- weight prep: transpose [k][n]->[n][k], split hi/lo, pad ----------------
__global__ void prep_weights(const float* __restrict__ sW1, const float* __restrict__ sW2,
                             const float* __restrict__ sW3, const float* __restrict__ jW1,
                             const float* __restrict__ jW2, const float* __restrict__ jW3) {
    int idx = blockIdx.x * blockDim.x + threadIdx.x;
    if (idx >= W1_ELEMS + W2_ELEMS + W3_ELEMS) return;
    int mlp = blockIdx.y;
    const float* W;
    int n, k, Kp, Kreal, N, hiE, loE;
    if (idx < W1_ELEMS) {
        Kp = W1_KP; n = idx / Kp; k = idx % Kp; N = 128;
        Kreal = mlp ? 96 : 32;
        W = mlp ? jW1 : sW1;
        hiE = 0; loE = W1_ELEMS;
    } else if (idx < W1_ELEMS + W2_ELEMS) {
        int li = idx - W1_ELEMS;
        Kp = W23_KP; n = li / Kp; k = li % Kp; N = 128;
        Kreal = 128;
        W = mlp ? jW2 : sW2;
        hiE = 2 * W1_ELEMS; loE = 2 * W1_ELEMS + W2_ELEMS;
    } else {
        int li = idx - W1_ELEMS - W2_ELEMS;
        Kp = W23_KP; n = li / Kp; k = li % Kp; N = 32;
        Kreal = 128;
        W = mlp ? jW3 : sW3;
        hiE = 2 * W1_ELEMS + 2 * W2_ELEMS; loE = hiE + W3_ELEMS;
    }
    float w = (k < Kreal) ? W[k * N + n] : 0.f;
    __nv_bfloat16 bh = __float2bfloat16(w);
    float r = w - __bfloat162float(bh);
    __nv_bfloat16 bl = __float2bfloat16(r);
    __nv_bfloat16* base = (__nv_bfloat16*)(g_wstage + (size_t)mlp * STAGE_BYTES);
    base[hiE + n * Kp + k] = bh;
    base[loE + n * Kp + k] = bl;
}

// ---------------- main tile kernel: 2 warp-groups, each a 64-row tile ----------------
template <bool JOIN, int NK1>
__global__ void __launch_bounds__(256, 1)
    mlp3_kernel(const float* __restrict__ feats, int off, int nShift, const float* __restrict__ prev,
                const float* __restrict__ b1, const float* __restrict__ b2,
                const float* __restrict__ b3, float* __restrict__ Y, int numTiles, int mlpIdx) {
    extern __shared__ char sm[];
    float* smF = (float*)sm;

    copy4(smF, (const float*)(g_wstage + (size_t)mlpIdx * STAGE_BYTES), STAGE_BYTES / 4);
    copy4(smF + OFF_BIAS / 4, b1, 128);
    copy4(smF + OFF_BIAS / 4 + 128, b2, 128);
    copy4(smF + OFF_BIAS / 4 + 256, b3, 32);
    __syncthreads();

    const uint32_t su = smem_u32(sm);
    const float* sB1 = smF + OFF_BIAS / 4;
    const float* sB2 = sB1 + 128;
    const float* sB3 = sB2 + 128;

    const int t = threadIdx.x;
    const int grp = t >> 7;        // 0 or 1
    const int tl = t & 127;        // thread within group
    const int wg = tl >> 5;        // warp within group (0..3)
    const int lane = t & 31;

    char* aHi = sm + OFF_A + grp * GRP_A_BYTES;
    char* aLo = aHi + GRP_A_LO;
    const uint32_t aHiU = su + OFF_A + grp * GRP_A_BYTES;
    const uint32_t aLoU = aHiU + GRP_A_LO;

    const int m0 = (wg & 1) * 32;      // rows within the group's 64-row tile
    const int n064 = (wg >> 1) * 64;   // N=128 layers
    const int n016 = (wg >> 1) * 16;   // N=32 layer
    const int arow = tl >> 1;          // assembly: 2 threads per row (64 rows)
    const int ahalf = tl & 1;

    float c[2][8][4];
    float c3[2][2][4];

    for (int tile = blockIdx.x * 2 + grp; tile < numTiles; tile += gridDim.x * 2) {
        // ---- assemble layer-1 input (bf16 hi/lo) ----
        if (JOIN) {
            int g = tile * 64 + arow;
            int bidx = g >> nShift, i = g & ((1 << nShift) - 1);
            const float4* frow =
                (const float4*)(feats + ((size_t)bidx * (NLEAF - 1) + off + i) * 32);
            const float4* crow =
                (const float4*)(prev + (((size_t)bidx << (nShift + 1)) + 2 * (size_t)i) * 32);
            int q0 = ahalf * 12;
#pragma unroll
            for (int jj = 0; jj < 12; jj++) {
                int q = q0 + jj;
                float4 v = (q < 8) ? frow[q] : crow[q - 8];
                store4A(aHi, aLo, arow, q * 4, v);
            }
        } else {
            const float4* xr = (const float4*)(feats + ((size_t)tile * 64 + arow) * 32);
            int q0 = ahalf * 4;
#pragma unroll
            for (int jj = 0; jj < 4; jj++) {
                int q = q0 + jj;
                store4A(aHi, aLo, arow, q * 4, xr[q]);
            }
        }
        bar_grp(grp);

        // ---- layer 1 ----
        layer_mma<NK1, 8, W1_KP>(aHiU, aLoU, su + OFF_W1H, su + OFF_W1L, c, m0, n064);
        bar_grp(grp);
        epi_to_A<8, true>(c, sB1, aHi, aLo, m0, n064);
        bar_grp(grp);

        // ---- layer 2 ----
        layer_mma<8, 8, W23_KP>(aHiU, aLoU, su + OFF_W2H, su + OFF_W2L, c, m0, n064);
        bar_grp(grp);
        epi_to_A<8, true>(c, sB2, aHi, aLo, m0, n064);
        bar_grp(grp);

        // ---- layer 3 (N=32, no relu) -> gmem ----
        layer_mma<8, 2, W23_KP>(aHiU, aLoU, su + OFF_W3H, su + OFF_W3L, c3, m0, n016);
        bar_grp(grp);  // A reads done before next tile's assembly overwrites
        {
            const int cb = n016 + (lane & 3) * 2;
            const int r0 = m0 + (lane >> 2);
#pragma unroll
            for (int mt = 0; mt < 2; mt++) {
#pragma unroll
                for (int nt = 0; nt < 2; nt++) {
                    int col = cb + nt * 8;
                    float2 bb = *(const float2*)(sB3 + col);
                    int r = r0 + mt * 16;
                    float2 o0 = make_float2(c3[mt][nt][0] + bb.x, c3[mt][nt][1] + bb.y);
                    float2 o1 = make_float2(c3[mt][nt][2] + bb.x, c3[mt][nt][3] + bb.y);
                    *(float2*)(Y + ((size_t)tile * 64 + r) * 32 + col) = o0;
                    *(float2*)(Y + ((size_t)tile * 64 + r + 8) * 32 + col) = o1;
                }
            }
        }
    }
}

__global__ void gather_kernel(const float* __restrict__ src, float* __restrict__ out) {
    int b = blockIdx.x * blockDim.x + threadIdx.x;
    if (b < B_DIM) out[b] = src[(size_t)b * 32];
}

extern "C" void kernel_launch(void* const* d_in, const int* in_sizes, int n_in, void* d_out,
                              int out_size) {
    const float* leaf = (const float*)d_in[0];
    const float* internal = (const float*)d_in[1];
    const float* sW1 = (const float*)d_in[2];
    const float* sb1 = (const float*)d_in[3];
    const float* sW2 = (const float*)d_in[4];
    const float* sb2 = (const float*)d_in[5];
    const float* sW3 = (const float*)d_in[6];
    const float* sb3 = (const float*)d_in[7];
    const float* jW1 = (const float*)d_in[8];
    const float* jb1 = (const float*)d_in[9];
    const float* jW2 = (const float*)d_in[10];
    const float* jb2 = (const float*)d_in[11];
    const float* jW3 = (const float*)d_in[12];
    const float* jb3 = (const float*)d_in[13];
    float* out = (float*)d_out;

    float *bufA, *bufB;
    cudaGetSymbolAddress((void**)&bufA, g_bufA);
    cudaGetSymbolAddress((void**)&bufB, g_bufB);

    cudaFuncSetAttribute(mlp3_kernel<false, 2>, cudaFuncAttributeMaxDynamicSharedMemorySize,
                         SM_BYTES);
    cudaFuncSetAttribute(mlp3_kernel<true, 6>, cudaFuncAttributeMaxDynamicSharedMemorySize,
                         SM_BYTES);

    int sms = 148;
    cudaDeviceGetAttribute(&sms, cudaDevAttrMultiProcessorCount, 0);

    const int totalW = W1_ELEMS + W2_ELEMS + W3_ELEMS;
    prep_weights<<<dim3((totalW + 255) / 256, 2), 256>>>(sW1, sW2, sW3, jW1, jW2, jW3);

    // leaf: 2048*1024 rows / 64 = 32768 tiles (2 per CTA per pass)
    mlp3_kernel<false, 2><<<sms, 256, SM_BYTES>>>(leaf, 0, 0, nullptr, sb1, sb2, sb3, bufA, 32768,
                                                  0);

    float* src = bufA;
    float* dst = bufB;
    int off = 0;
    for (int sh = 9; sh >= 0; sh--) {
        int n = 1 << sh;
        int tiles = 32 * n;  // 2048*n/64
        mlp3_kernel<true, 6><<<sms, 256, SM_BYTES>>>(internal, off, sh, src, jb1, jb2, jb3, dst,
                                                     tiles, 1);
        off += n;
        float* tmp = src;
        src = dst;
        dst = tmp;
    }
    gather_kernel<<<(B_DIM + 255) / 256, 256>>>(src, out);
}